// round 16
// baseline (speedup 1.0000x reference)
#include <cuda_runtime.h>
#include <cuda_bf16.h>
#include <cstdint>

#define BB 4
#define SS 1024
#define DD 1024
#define HH 16
#define DH 64
#define MTOT (BB * SS)          // 4096

// ================= scratch (static device memory; no allocs) =================
__device__ __nv_bfloat16 g_q_hi[MTOT * DD], g_q_lo[MTOT * DD];
__device__ __nv_bfloat16 g_k_hi[MTOT * DD], g_k_lo[MTOT * DD];
__device__ __nv_bfloat16 g_v_hi[MTOT * DD], g_v_lo[MTOT * DD];
__device__ __nv_bfloat16 g_wq_hi[DD * DD], g_wq_lo[DD * DD];   // W^T [n][k]
__device__ __nv_bfloat16 g_wk_hi[DD * DD], g_wk_lo[DD * DD];
__device__ __nv_bfloat16 g_wv_hi[DD * DD], g_wv_lo[DD * DD];
__device__ __nv_bfloat16 g_wo_hi[DD * DD], g_wo_lo[DD * DD];
// projected heads
__device__ __nv_bfloat16 g_qph[BB * HH * SS * DH], g_qpl[BB * HH * SS * DH]; // [B,H,S,dh]
__device__ __nv_bfloat16 g_kph[BB * HH * SS * DH], g_kpl[BB * HH * SS * DH];
__device__ __nv_bfloat16 g_vth[BB * HH * DH * SS], g_vtl[BB * HH * DH * SS]; // [B,H,dh,S]
__device__ __nv_bfloat16 g_cx_hi[MTOT * DD], g_cx_lo[MTOT * DD];             // ctx [m][1024]

// ================= helpers =================
static __device__ __forceinline__ uint32_t smem_u32(const void* p) {
    uint32_t a;
    asm("{ .reg .u64 t; cvta.to.shared.u64 t, %1; cvt.u32.u64 %0, t; }"
        : "=r"(a) : "l"(p));
    return a;
}

#define CP_ASYNC16(dst, src) \
    asm volatile("cp.async.cg.shared.global [%0], [%1], 16;" \
                 :: "r"(dst), "l"(src) : "memory")
#define CP_COMMIT()  asm volatile("cp.async.commit_group;" ::: "memory")
#define CP_WAIT(n)   asm volatile("cp.async.wait_group %0;" :: "n"(n) : "memory")

#define LDSM_X4(r, a) \
    asm volatile("ldmatrix.sync.aligned.m8n8.x4.shared.b16 {%0,%1,%2,%3}, [%4];" \
                 : "=r"((r)[0]), "=r"((r)[1]), "=r"((r)[2]), "=r"((r)[3]) : "r"(a))
#define LDSM_X2(r, a) \
    asm volatile("ldmatrix.sync.aligned.m8n8.x2.shared.b16 {%0,%1}, [%2];" \
                 : "=r"((r)[0]), "=r"((r)[1]) : "r"(a))
#define MMA16816(c, a, b) \
    asm volatile("mma.sync.aligned.m16n8k16.row.col.f32.bf16.bf16.f32 " \
                 "{%0,%1,%2,%3}, {%4,%5,%6,%7}, {%8,%9}, {%0,%1,%2,%3};" \
                 : "+f"((c)[0]), "+f"((c)[1]), "+f"((c)[2]), "+f"((c)[3]) \
                 : "r"((a)[0]), "r"((a)[1]), "r"((a)[2]), "r"((a)[3]), \
                   "r"((b)[0]), "r"((b)[1]))

#define STG_CS_F2(ptr, vx, vy) \
    asm volatile("st.global.cs.v2.f32 [%0], {%1, %2};" \
                 :: "l"(ptr), "f"(vx), "f"(vy) : "memory")

#define BAR_PAIR(id) \
    asm volatile("bar.sync %0, 64;" :: "r"(id) : "memory")

static __device__ __forceinline__ uint32_t pack_bf2(float x, float y) {
    __nv_bfloat16 a = __float2bfloat16(x), b = __float2bfloat16(y);
    uint16_t ua = *(uint16_t*)&a, ub = *(uint16_t*)&b;
    return (uint32_t)ua | ((uint32_t)ub << 16);
}
static __device__ __forceinline__ void split_bf2(float x, float y,
                                                 uint32_t& hi, uint32_t& lo) {
    __nv_bfloat16 hx = __float2bfloat16(x), hy = __float2bfloat16(y);
    float rx = x - __bfloat162float(hx);
    float ry = y - __bfloat162float(hy);
    uint16_t ux = *(uint16_t*)&hx, uy = *(uint16_t*)&hy;
    hi = (uint32_t)ux | ((uint32_t)uy << 16);
    lo = pack_bf2(rx, ry);
}
// cheap truncation split (hi = exact bf16 truncation via byte-perm)
static __device__ __forceinline__ void split_bf2_trunc(float x, float y,
                                                       uint32_t& hi, uint32_t& lo) {
    uint32_t bx = __float_as_uint(x), by = __float_as_uint(y);
    hi = __byte_perm(bx, by, 0x7632);
    float rx = x - __uint_as_float(bx & 0xFFFF0000u);
    float ry = y - __uint_as_float(by & 0xFFFF0000u);
    asm("cvt.rn.bf16x2.f32 %0, %1, %2;" : "=r"(lo) : "f"(ry), "f"(rx));
}

// ================= conversion kernels =================
__global__ __launch_bounds__(256) void cvt_split_kernel(
    const float* __restrict__ q, const float* __restrict__ k,
    const float* __restrict__ v)
{
    const float* src;
    __nv_bfloat16 *hi, *lo;
    if (blockIdx.y == 0)      { src = q; hi = g_q_hi; lo = g_q_lo; }
    else if (blockIdx.y == 1) { src = k; hi = g_k_hi; lo = g_k_lo; }
    else                      { src = v; hi = g_v_hi; lo = g_v_lo; }

    int i = (blockIdx.x * 256 + threadIdx.x) * 4;
    float4 f = *(const float4*)(src + i);
    __nv_bfloat16 h[4], l[4];
    float val[4] = {f.x, f.y, f.z, f.w};
    #pragma unroll
    for (int j = 0; j < 4; j++) {
        h[j] = __float2bfloat16(val[j]);
        l[j] = __float2bfloat16(val[j] - __bfloat162float(h[j]));
    }
    *(uint2*)(hi + i) = *(uint2*)h;
    *(uint2*)(lo + i) = *(uint2*)l;
}

__global__ __launch_bounds__(256) void cvt_wt4_kernel(
    const float* __restrict__ Wq, const float* __restrict__ Wk,
    const float* __restrict__ Wv, const float* __restrict__ Wo)
{
    const float* W;
    __nv_bfloat16 *hi, *lo;
    int interleaved = 1;
    if (blockIdx.z == 0)      { W = Wq; hi = g_wq_hi; lo = g_wq_lo; }
    else if (blockIdx.z == 1) { W = Wk; hi = g_wk_hi; lo = g_wk_lo; }
    else if (blockIdx.z == 2) { W = Wv; hi = g_wv_hi; lo = g_wv_lo; }
    else                      { W = Wo; hi = g_wo_hi; lo = g_wo_lo; interleaved = 0; }

    __shared__ float t[32][33];
    const int tx = threadIdx.x, ty = threadIdx.y;
    const int k0 = blockIdx.x * 32, n0 = blockIdx.y * 32;

    #pragma unroll
    for (int i = 0; i < 4; i++) {
        int k = k0 + ty + i * 8;
        int n = n0 + tx;
        size_t a = interleaved ? ((size_t)(n >> 6) * 65536 + (size_t)k * 64 + (n & 63))
                               : ((size_t)k * 1024 + n);
        t[ty + i * 8][tx] = W[a];
    }
    __syncthreads();
    #pragma unroll
    for (int i = 0; i < 4; i++) {
        int n = n0 + ty + i * 8;
        int k = k0 + tx;
        float v = t[tx][ty + i * 8];
        __nv_bfloat16 h = __float2bfloat16(v);
        hi[(size_t)n * 1024 + k] = h;
        lo[(size_t)n * 1024 + k] = __float2bfloat16(v - __bfloat162float(h));
    }
}

// ================= mma.sync bf16-split GEMM core (128x64, 3 CTA/SM) =========
#define GK 40
#define G_AH 0
#define G_AL 10240
#define G_BH 20480
#define G_BL 25600
#define G_STAGE 30720
#define GEMM_SMEM (2 * G_STAGE)          // 61440

static __device__ __forceinline__ void gemm_core(
    const __nv_bfloat16* __restrict__ Ahi, const __nv_bfloat16* __restrict__ Alo,
    const __nv_bfloat16* __restrict__ Bhi, const __nv_bfloat16* __restrict__ Blo,
    const float* __restrict__ bias, float* __restrict__ Cf,
    __nv_bfloat16* __restrict__ Ch, __nv_bfloat16* __restrict__ Cl, int mode,
    char* sm)
{
    const uint32_t smb = smem_u32(sm);
    const int tid    = threadIdx.x;
    const int lane   = tid & 31;
    const int warp   = tid >> 5;
    const int warp_m = warp >> 1;
    const int warp_n = warp & 1;
    const int m0 = blockIdx.x * 128;
    const int n0 = blockIdx.y * 64;

    const uint32_t aoff = ((warp_m * 64 + (lane & 15)) * GK + ((lane >> 4) * 8)) * 2;
    const uint32_t boff4 = ((warp_n * 32 + ((lane >> 4) & 1) * 8 + (lane & 7)) * GK
                            + ((lane >> 3) & 1) * 8) * 2;

    float acc[4][4][4] = {};

    auto issue = [&](int c) {
        const uint32_t sb = smb + (c & 1) * G_STAGE;
        const int k0 = c * 32;
        #pragma unroll
        for (int j = 0; j < 4; j++) {
            int lin = tid + j * 128;
            int row = lin >> 2;
            int cg  = lin & 3;
            uint32_t so = (uint32_t)(row * 80 + cg * 16);
            size_t ga = (size_t)(m0 + row) * DD + k0 + cg * 8;
            CP_ASYNC16(sb + G_AH + so, Ahi + ga);
            CP_ASYNC16(sb + G_AL + so, Alo + ga);
        }
        #pragma unroll
        for (int j = 0; j < 2; j++) {
            int lin = tid + j * 128;
            int row = lin >> 2;
            int cg  = lin & 3;
            uint32_t so = (uint32_t)(row * 80 + cg * 16);
            size_t gb = (size_t)(n0 + row) * DD + k0 + cg * 8;
            CP_ASYNC16(sb + G_BH + so, Bhi + gb);
            CP_ASYNC16(sb + G_BL + so, Blo + gb);
        }
    };

    issue(0);
    CP_COMMIT();

    for (int c = 0; c < DD / 32; c++) {
        if (c + 1 < DD / 32) {
            issue(c + 1);
            CP_COMMIT();
            CP_WAIT(1);
        } else {
            CP_WAIT(0);
        }
        __syncthreads();

        const uint32_t sb = smb + (c & 1) * G_STAGE;
        #pragma unroll
        for (int kk = 0; kk < 2; kk++) {
            const uint32_t kby = kk * 32;
            uint32_t ah[4][4], al[4][4];
            #pragma unroll
            for (int mf = 0; mf < 4; mf++) {
                uint32_t ra = sb + aoff + (uint32_t)(mf * 16 * 80) + kby;
                LDSM_X4(ah[mf], ra + G_AH);
                LDSM_X4(al[mf], ra + G_AL);
            }
            uint32_t bh4[2][4], bl4[2][4];
            #pragma unroll
            for (int nfp = 0; nfp < 2; nfp++) {
                uint32_t rb = sb + boff4 + (uint32_t)(nfp * 16 * 80) + kby;
                LDSM_X4(bh4[nfp], rb + G_BH);
                LDSM_X4(bl4[nfp], rb + G_BL);
            }
            #pragma unroll
            for (int mf = 0; mf < 4; mf++)
                #pragma unroll
                for (int nf = 0; nf < 4; nf++) {
                    uint32_t* bh = &bh4[nf >> 1][(nf & 1) * 2];
                    uint32_t* bl = &bl4[nf >> 1][(nf & 1) * 2];
                    MMA16816(acc[mf][nf], ah[mf], bh);
                    MMA16816(acc[mf][nf], ah[mf], bl);
                    MMA16816(acc[mf][nf], al[mf], bh);
                }
        }
        __syncthreads();
    }

    const int lr = lane >> 2;
    const int lc = (lane & 3) * 2;
    #pragma unroll
    for (int mf = 0; mf < 4; mf++) {
        #pragma unroll
        for (int nf = 0; nf < 4; nf++) {
            int n = n0 + warp_n * 32 + nf * 8 + lc;
            float bv0 = bias[n], bv1 = bias[n + 1];
            #pragma unroll
            for (int half = 0; half < 2; half++) {
                int m = m0 + warp_m * 64 + mf * 16 + lr + half * 8;
                float x = acc[mf][nf][half * 2 + 0] + bv0;
                float y = acc[mf][nf][half * 2 + 1] + bv1;
                if (mode == 1) {
                    *(float2*)(Cf + (size_t)m * DD + n) = make_float2(x, y);
                } else {
                    uint32_t phi, plo;
                    split_bf2(x, y, phi, plo);
                    int bidx = m >> 10, s = m & 1023;
                    int h = n >> 6, e = n & 63;
                    if (mode == 0) {
                        size_t off = (((size_t)bidx * HH + h) * SS + s) * DH + e;
                        *(uint32_t*)(Ch + off) = phi;
                        *(uint32_t*)(Cl + off) = plo;
                    } else {
                        size_t off = (((size_t)bidx * HH + h) * DH + e) * SS + s;
                        Ch[off]      = *(__nv_bfloat16*)&phi;
                        Ch[off + SS] = ((__nv_bfloat16*)&phi)[1];
                        Cl[off]      = *(__nv_bfloat16*)&plo;
                        Cl[off + SS] = ((__nv_bfloat16*)&plo)[1];
                    }
                }
            }
        }
    }
}

__global__ __launch_bounds__(128, 3) void qkv_gemm_kernel(
    const float* __restrict__ bq, const float* __restrict__ bk,
    const float* __restrict__ bv)
{
    extern __shared__ char sm[];
    const int z = blockIdx.z;
    if (z == 0)
        gemm_core(g_q_hi, g_q_lo, g_wq_hi, g_wq_lo, bq, nullptr, g_qph, g_qpl, 0, sm);
    else if (z == 1)
        gemm_core(g_k_hi, g_k_lo, g_wk_hi, g_wk_lo, bk, nullptr, g_kph, g_kpl, 0, sm);
    else
        gemm_core(g_v_hi, g_v_lo, g_wv_hi, g_wv_lo, bv, nullptr, g_vth, g_vtl, 2, sm);
}

__global__ __launch_bounds__(128, 3) void outproj_gemm_kernel(
    const float* __restrict__ bo, float* __restrict__ out)
{
    extern __shared__ char sm[];
    gemm_core(g_cx_hi, g_cx_lo, g_wo_hi, g_wo_lo, bo, out, nullptr, nullptr, 1, sm);
}

// ================= fused single-pass attention (warp-pair pipelines) =========
//   q=32, 64-key chunks. 8 warps = 2 q-halves x 4 key-quarters.
//   Each kq pair owns a private K/V slice + its own cp.async pipeline,
//   synced by a 64-thread named barrier (no per-chunk CTA syncs). 2 CTAs/SM.
#define AQ_H 0                           // q hi: 32*144 = 4608
#define AQ_L 4608
#define AKV 9216
#define P_KH 0                           // K quarter hi: 16*144 = 2304
#define P_KL 2304
#define P_VH 4608                        // V slice hi: 64*48 = 3072
#define P_VL 7680
#define PAIR_B 10752
#define ST_STAGE (4 * PAIR_B)            // 43008
#define ATT_SMEM (AKV + 2 * ST_STAGE)    // 95232

__global__ __launch_bounds__(256, 2) void attn_kernel(float* __restrict__ score_out)
{
    extern __shared__ char sm[];
    __shared__ float s_part[8][16];
    __shared__ float s_inv[32];
    const uint32_t smb = smem_u32(sm);

    const int bh  = blockIdx.y;
    const int q0  = blockIdx.x * 32;
    const int tid = threadIdx.x;
    const int lane = tid & 31;
    const int w    = tid >> 5;
    const int qh   = w >> 2;     // q half: rows qh*16..+16
    const int kq   = w & 3;      // key quarter (pair id)

    const __nv_bfloat16* qph = g_qph + (size_t)bh * SS * DH;
    const __nv_bfloat16* qpl = g_qpl + (size_t)bh * SS * DH;
    const __nv_bfloat16* kph = g_kph + (size_t)bh * SS * DH;
    const __nv_bfloat16* kpl = g_kpl + (size_t)bh * SS * DH;
    const __nv_bfloat16* vth = g_vth + (size_t)bh * DH * SS;
    const __nv_bfloat16* vtl = g_vtl + (size_t)bh * DH * SS;

    // ---- load q tile (32 x 64) hi/lo into smem ----
    {
        int row = tid >> 3, grp = tid & 7;
        size_t src = (size_t)(q0 + row) * DH + grp * 8;
        uint32_t dst = (uint32_t)(row * 144 + grp * 16);
        *(uint4*)(sm + AQ_H + dst) = *(const uint4*)(qph + src);
        *(uint4*)(sm + AQ_L + dst) = *(const uint4*)(qpl + src);
    }

    const uint32_t a_off = ((qh * 16 + (lane & 15)) * 144 + (lane >> 4) * 16);
    // local-slice ldmatrix offsets (bytes)
    const uint32_t bk4_off = (((lane >> 4) & 1) * 8 + (lane & 7)) * 144
                           + ((lane >> 3) & 1) * 16;
    const uint32_t bv4_off = (((lane >> 4) & 1) * 8 + (lane & 7)) * 48
                           + ((lane >> 3) & 1) * 16;

    const int t2 = qh * 32 + lane;       // 0..63 within pair

    auto issueKV = [&](int c) {
        const uint32_t sb = smb + AKV + (c & 1) * ST_STAGE + kq * PAIR_B;
        const int c0 = c * 64;
        #pragma unroll
        for (int i = 0; i < 2; i++) {
            int id = t2 + i * 64;         // 0..127
            int row = id >> 3, grp = id & 7;
            uint32_t so = (uint32_t)(row * 144 + grp * 16);
            size_t ks = (size_t)(c0 + kq * 16 + row) * DH + grp * 8;
            CP_ASYNC16(sb + P_KH + so, kph + ks);
            CP_ASYNC16(sb + P_KL + so, kpl + ks);
        }
        #pragma unroll
        for (int i = 0; i < 2; i++) {
            int id = t2 + i * 64;         // 0..127
            int e = id >> 1, g = id & 1;
            uint32_t so = (uint32_t)(e * 48 + g * 16);
            size_t vs = (size_t)e * SS + c0 + kq * 16 + g * 8;
            CP_ASYNC16(sb + P_VH + so, vth + vs);
            CP_ASYNC16(sb + P_VL + so, vtl + vs);
        }
    };

    issueKV(0);
    CP_COMMIT();
    __syncthreads();   // q tile visible to all warps

    // ---- hoist Q fragments into registers (loop-invariant) ----
    uint32_t qfh[4][4], qfl[4][4];
    #pragma unroll
    for (int kk = 0; kk < 4; kk++) {
        uint32_t ra = smb + a_off + kk * 32;
        LDSM_X4(qfh[kk], ra + AQ_H);
        LDSM_X4(qfl[kk], ra + AQ_L);
    }

    float ctx[8][4] = {};
    float psum0 = 0.f, psum1 = 0.f;

    float* grow0 = score_out + ((size_t)bh * SS + q0 + qh * 16 + (lane >> 2)) * SS;
    float* grow1 = grow0 + (size_t)8 * SS;
    const int lc = (lane & 3) * 2;
    const int barid = kq + 1;

    for (int c = 0; c < 16; c++) {
        if (c < 15) { issueKV(c + 1); CP_COMMIT(); CP_WAIT(1); }
        else        { CP_WAIT(0); }
        BAR_PAIR(barid);   // pair's chunk c data visible

        const uint32_t sb = smb + AKV + (c & 1) * ST_STAGE + kq * PAIR_B;

        // S = Q K^T for this warp's 16 q-rows x 16 keys
        float sacc[2][4] = {};
        #pragma unroll
        for (int kk = 0; kk < 4; kk++) {
            uint32_t kb4[4], kl4[4];
            uint32_t rb = sb + bk4_off + kk * 32;
            LDSM_X4(kb4, rb + P_KH);
            LDSM_X4(kl4, rb + P_KL);
            MMA16816(sacc[0], qfh[kk], (kb4));
            MMA16816(sacc[1], qfh[kk], (kb4 + 2));
            MMA16816(sacc[0], qfh[kk], (kl4));
            MMA16816(sacc[1], qfh[kk], (kl4 + 2));
            MMA16816(sacc[0], qfl[kk], (kb4));
            MMA16816(sacc[1], qfl[kk], (kb4 + 2));
        }

        // exp in registers (no max: |logit| < ~4), stream to gmem, build P frags
        float e0 = __expf(sacc[0][0] * 0.125f);
        float e1 = __expf(sacc[0][1] * 0.125f);
        float e2 = __expf(sacc[0][2] * 0.125f);
        float e3 = __expf(sacc[0][3] * 0.125f);
        float f0 = __expf(sacc[1][0] * 0.125f);
        float f1 = __expf(sacc[1][1] * 0.125f);
        float f2 = __expf(sacc[1][2] * 0.125f);
        float f3 = __expf(sacc[1][3] * 0.125f);

        int keyb = c * 64 + kq * 16 + lc;
        STG_CS_F2(grow0 + keyb,     e0, e1);
        STG_CS_F2(grow1 + keyb,     e2, e3);
        STG_CS_F2(grow0 + keyb + 8, f0, f1);
        STG_CS_F2(grow1 + keyb + 8, f2, f3);

        psum0 += (e0 + e1) + (f0 + f1);
        psum1 += (e2 + e3) + (f2 + f3);

        uint32_t pah[4], pal[4];
        split_bf2_trunc(e0, e1, pah[0], pal[0]);
        split_bf2_trunc(e2, e3, pah[1], pal[1]);
        split_bf2_trunc(f0, f1, pah[2], pal[2]);
        split_bf2_trunc(f2, f3, pah[3], pal[3]);

        // ctx += P V (k = this pair's 16 keys)
        #pragma unroll
        for (int nf2 = 0; nf2 < 4; nf2++) {
            uint32_t vh4[4], vl4[4];
            uint32_t rb = sb + bv4_off + (uint32_t)(nf2 * 16 * 48);
            LDSM_X4(vh4, rb + P_VH);
            LDSM_X4(vl4, rb + P_VL);
            MMA16816(ctx[2 * nf2],     pah, (vh4));
            MMA16816(ctx[2 * nf2 + 1], pah, (vh4 + 2));
            MMA16816(ctx[2 * nf2],     pah, (vl4));
            MMA16816(ctx[2 * nf2 + 1], pah, (vl4 + 2));
            MMA16816(ctx[2 * nf2],     pal, (vh4));
            MMA16816(ctx[2 * nf2 + 1], pal, (vh4 + 2));
        }
        BAR_PAIR(barid);   // both warps done reading before next overwrite
    }

    __threadfence();   // score exp writes visible before read-back

    // ---- row-sum reduce -> s_part ----
    psum0 += __shfl_xor_sync(0xFFFFFFFFu, psum0, 1);
    psum0 += __shfl_xor_sync(0xFFFFFFFFu, psum0, 2);
    psum1 += __shfl_xor_sync(0xFFFFFFFFu, psum1, 1);
    psum1 += __shfl_xor_sync(0xFFFFFFFFu, psum1, 2);
    if ((lane & 3) == 0) {
        s_part[w][lane >> 2]       = psum0;
        s_part[w][(lane >> 2) + 8] = psum1;
    }
    __syncthreads();   // all pairs done with loop; s_part complete

    // ---- ctx partials to smem (overlay KV stages) ----
    float* red = (float*)(sm + AKV);
    {
        int rl = lane >> 2;
        #pragma unroll
        for (int nf = 0; nf < 8; nf++) {
            int col = nf * 8 + lc;
            *(float2*)&red[w * 1024 + rl * 64 + col] =
                make_float2(ctx[nf][0], ctx[nf][1]);
            *(float2*)&red[w * 1024 + (rl + 8) * 64 + col] =
                make_float2(ctx[nf][2], ctx[nf][3]);
        }
    }

    if (tid < 32) {
        int qhh = tid >> 4, lr = tid & 15;
        float s = s_part[qhh * 4 + 0][lr] + s_part[qhh * 4 + 1][lr]
                + s_part[qhh * 4 + 2][lr] + s_part[qhh * 4 + 3][lr];
        s_inv[tid] = 1.f / s;
    }
    __syncthreads();

    // ---- combine ctx, normalize, write bf16 hi/lo ----
    {
        int row = tid >> 3;              // 0..31
        int cg  = (tid & 7) * 8;
        int qhh = row >> 4, lr = row & 15;
        float iv = s_inv[row];
        float o[8];
        #pragma unroll
        for (int j = 0; j < 8; j++) {
            o[j] = (red[(qhh * 4 + 0) * 1024 + lr * 64 + cg + j]
                  + red[(qhh * 4 + 1) * 1024 + lr * 64 + cg + j]
                  + red[(qhh * 4 + 2) * 1024 + lr * 64 + cg + j]
                  + red[(qhh * 4 + 3) * 1024 + lr * 64 + cg + j]) * iv;
        }
        const int b = bh >> 4;
        const int h = bh & 15;
        size_t off = ((size_t)b * SS + q0 + row) * DD + h * DH + cg;
        __align__(16) __nv_bfloat16 hb[8], lb[8];
        #pragma unroll
        for (int j = 0; j < 8; j++) {
            hb[j] = __float2bfloat16(o[j]);
            lb[j] = __float2bfloat16(o[j] - __bfloat162float(hb[j]));
        }
        *(uint4*)(g_cx_hi + off) = *(uint4*)hb;
        *(uint4*)(g_cx_lo + off) = *(uint4*)lb;
    }

    // ---- score normalize epilogue (L2 read-back) ----
    {
        float* base = score_out + ((size_t)bh * SS + q0) * SS;
        for (int i = tid; i < 32 * 256; i += 256) {
            int row = i >> 8, g4 = i & 255;
            float4* p = (float4*)(base + (size_t)row * SS) + g4;
            float4 v = __ldcg(p);
            float iv = s_inv[row];
            v.x *= iv; v.y *= iv; v.z *= iv; v.w *= iv;
            __stcs(p, v);
        }
    }
}

// ============================================================
extern "C" void kernel_launch(void* const* d_in, const int* in_sizes, int n_in,
                              void* d_out, int out_size)
{
    const float* q  = (const float*)d_in[0];
    const float* k  = (const float*)d_in[1];
    const float* v  = (const float*)d_in[2];
    const float* Wq = (const float*)d_in[3];
    const float* bq = (const float*)d_in[4];
    const float* Wk = (const float*)d_in[5];
    const float* bk = (const float*)d_in[6];
    const float* Wv = (const float*)d_in[7];
    const float* bv = (const float*)d_in[8];
    const float* Wo = (const float*)d_in[9];
    const float* bo = (const float*)d_in[10];

    float* out   = (float*)d_out;
    float* score = out + (size_t)BB * SS * DD;

    cudaFuncSetAttribute(attn_kernel,
                         cudaFuncAttributeMaxDynamicSharedMemorySize, ATT_SMEM);
    cudaFuncSetAttribute(qkv_gemm_kernel,
                         cudaFuncAttributeMaxDynamicSharedMemorySize, GEMM_SMEM);
    cudaFuncSetAttribute(outproj_gemm_kernel,
                         cudaFuncAttributeMaxDynamicSharedMemorySize, GEMM_SMEM);

    // launch 1: activation conversions (fused)
    {
        dim3 g(MTOT * DD / 1024, 3);
        cvt_split_kernel<<<g, 256>>>(q, k, v);
    }
    // launch 2: all weight conversions (fused)
    {
        dim3 g(32, 32, 4), b(32, 8);
        cvt_wt4_kernel<<<g, b>>>(Wq, Wk, Wv, Wo);
    }
    // launch 3: fused QKV projections
    {
        dim3 g(MTOT / 128, DD / 64, 3);
        qkv_gemm_kernel<<<g, 128, GEMM_SMEM>>>(bq, bk, bv);
    }
    // launch 4: fused single-pass attention
    {
        dim3 g(SS / 32, BB * HH);
        attn_kernel<<<g, 256, ATT_SMEM>>>(score);
    }
    // launch 5: output projection
    {
        dim3 g(MTOT / 128, DD / 64);
        outproj_gemm_kernel<<<g, 128, GEMM_SMEM>>>(bo, out);
    }
}

// round 17
// speedup vs baseline: 1.0398x; 1.0398x over previous
#include <cuda_runtime.h>
#include <cuda_bf16.h>
#include <cstdint>

#define BB 4
#define SS 1024
#define DD 1024
#define HH 16
#define DH 64
#define MTOT (BB * SS)          // 4096

// ================= scratch (static device memory; no allocs) =================
__device__ __nv_bfloat16 g_q_hi[MTOT * DD], g_q_lo[MTOT * DD];
__device__ __nv_bfloat16 g_k_hi[MTOT * DD], g_k_lo[MTOT * DD];
__device__ __nv_bfloat16 g_v_hi[MTOT * DD], g_v_lo[MTOT * DD];
__device__ __nv_bfloat16 g_wq_hi[DD * DD], g_wq_lo[DD * DD];   // W^T [n][k]
__device__ __nv_bfloat16 g_wk_hi[DD * DD], g_wk_lo[DD * DD];
__device__ __nv_bfloat16 g_wv_hi[DD * DD], g_wv_lo[DD * DD];
__device__ __nv_bfloat16 g_wo_hi[DD * DD], g_wo_lo[DD * DD];
// projected heads
__device__ __nv_bfloat16 g_qph[BB * HH * SS * DH], g_qpl[BB * HH * SS * DH]; // [B,H,S,dh]
__device__ __nv_bfloat16 g_kph[BB * HH * SS * DH], g_kpl[BB * HH * SS * DH];
__device__ __nv_bfloat16 g_vth[BB * HH * DH * SS], g_vtl[BB * HH * DH * SS]; // [B,H,dh,S]
__device__ __nv_bfloat16 g_cx_hi[MTOT * DD], g_cx_lo[MTOT * DD];             // ctx [m][1024]

// ================= helpers =================
static __device__ __forceinline__ uint32_t smem_u32(const void* p) {
    uint32_t a;
    asm("{ .reg .u64 t; cvta.to.shared.u64 t, %1; cvt.u32.u64 %0, t; }"
        : "=r"(a) : "l"(p));
    return a;
}

#define CP_ASYNC16(dst, src) \
    asm volatile("cp.async.cg.shared.global [%0], [%1], 16;" \
                 :: "r"(dst), "l"(src) : "memory")
#define CP_COMMIT()  asm volatile("cp.async.commit_group;" ::: "memory")
#define CP_WAIT(n)   asm volatile("cp.async.wait_group %0;" :: "n"(n) : "memory")

#define LDSM_X4(r, a) \
    asm volatile("ldmatrix.sync.aligned.m8n8.x4.shared.b16 {%0,%1,%2,%3}, [%4];" \
                 : "=r"((r)[0]), "=r"((r)[1]), "=r"((r)[2]), "=r"((r)[3]) : "r"(a))
#define LDSM_X2(r, a) \
    asm volatile("ldmatrix.sync.aligned.m8n8.x2.shared.b16 {%0,%1}, [%2];" \
                 : "=r"((r)[0]), "=r"((r)[1]) : "r"(a))
#define MMA16816(c, a, b) \
    asm volatile("mma.sync.aligned.m16n8k16.row.col.f32.bf16.bf16.f32 " \
                 "{%0,%1,%2,%3}, {%4,%5,%6,%7}, {%8,%9}, {%0,%1,%2,%3};" \
                 : "+f"((c)[0]), "+f"((c)[1]), "+f"((c)[2]), "+f"((c)[3]) \
                 : "r"((a)[0]), "r"((a)[1]), "r"((a)[2]), "r"((a)[3]), \
                   "r"((b)[0]), "r"((b)[1]))

#define STG_CS_F2(ptr, vx, vy) \
    asm volatile("st.global.cs.v2.f32 [%0], {%1, %2};" \
                 :: "l"(ptr), "f"(vx), "f"(vy) : "memory")
// L2 write-back (evict-normal): keep unnormalized scores L2-resident for read-back
#define STG_CG_F2(ptr, vx, vy) \
    asm volatile("st.global.cg.v2.f32 [%0], {%1, %2};" \
                 :: "l"(ptr), "f"(vx), "f"(vy) : "memory")

static __device__ __forceinline__ uint32_t pack_bf2(float x, float y) {
    __nv_bfloat16 a = __float2bfloat16(x), b = __float2bfloat16(y);
    uint16_t ua = *(uint16_t*)&a, ub = *(uint16_t*)&b;
    return (uint32_t)ua | ((uint32_t)ub << 16);
}
static __device__ __forceinline__ void split_bf2(float x, float y,
                                                 uint32_t& hi, uint32_t& lo) {
    __nv_bfloat16 hx = __float2bfloat16(x), hy = __float2bfloat16(y);
    float rx = x - __bfloat162float(hx);
    float ry = y - __bfloat162float(hy);
    uint16_t ux = *(uint16_t*)&hx, uy = *(uint16_t*)&hy;
    hi = (uint32_t)ux | ((uint32_t)uy << 16);
    lo = pack_bf2(rx, ry);
}
// cheap truncation split (hi = exact bf16 truncation via byte-perm)
static __device__ __forceinline__ void split_bf2_trunc(float x, float y,
                                                       uint32_t& hi, uint32_t& lo) {
    uint32_t bx = __float_as_uint(x), by = __float_as_uint(y);
    hi = __byte_perm(bx, by, 0x7632);
    float rx = x - __uint_as_float(bx & 0xFFFF0000u);
    float ry = y - __uint_as_float(by & 0xFFFF0000u);
    asm("cvt.rn.bf16x2.f32 %0, %1, %2;" : "=r"(lo) : "f"(ry), "f"(rx));
}

// ================= conversion kernels =================
__global__ __launch_bounds__(256) void cvt_split_kernel(
    const float* __restrict__ q, const float* __restrict__ k,
    const float* __restrict__ v)
{
    const float* src;
    __nv_bfloat16 *hi, *lo;
    if (blockIdx.y == 0)      { src = q; hi = g_q_hi; lo = g_q_lo; }
    else if (blockIdx.y == 1) { src = k; hi = g_k_hi; lo = g_k_lo; }
    else                      { src = v; hi = g_v_hi; lo = g_v_lo; }

    int i = (blockIdx.x * 256 + threadIdx.x) * 4;
    float4 f = *(const float4*)(src + i);
    __nv_bfloat16 h[4], l[4];
    float val[4] = {f.x, f.y, f.z, f.w};
    #pragma unroll
    for (int j = 0; j < 4; j++) {
        h[j] = __float2bfloat16(val[j]);
        l[j] = __float2bfloat16(val[j] - __bfloat162float(h[j]));
    }
    *(uint2*)(hi + i) = *(uint2*)h;
    *(uint2*)(lo + i) = *(uint2*)l;
}

__global__ __launch_bounds__(256) void cvt_wt4_kernel(
    const float* __restrict__ Wq, const float* __restrict__ Wk,
    const float* __restrict__ Wv, const float* __restrict__ Wo)
{
    const float* W;
    __nv_bfloat16 *hi, *lo;
    int interleaved = 1;
    if (blockIdx.z == 0)      { W = Wq; hi = g_wq_hi; lo = g_wq_lo; }
    else if (blockIdx.z == 1) { W = Wk; hi = g_wk_hi; lo = g_wk_lo; }
    else if (blockIdx.z == 2) { W = Wv; hi = g_wv_hi; lo = g_wv_lo; }
    else                      { W = Wo; hi = g_wo_hi; lo = g_wo_lo; interleaved = 0; }

    __shared__ float t[32][33];
    const int tx = threadIdx.x, ty = threadIdx.y;
    const int k0 = blockIdx.x * 32, n0 = blockIdx.y * 32;

    #pragma unroll
    for (int i = 0; i < 4; i++) {
        int k = k0 + ty + i * 8;
        int n = n0 + tx;
        size_t a = interleaved ? ((size_t)(n >> 6) * 65536 + (size_t)k * 64 + (n & 63))
                               : ((size_t)k * 1024 + n);
        t[ty + i * 8][tx] = W[a];
    }
    __syncthreads();
    #pragma unroll
    for (int i = 0; i < 4; i++) {
        int n = n0 + ty + i * 8;
        int k = k0 + tx;
        float v = t[tx][ty + i * 8];
        __nv_bfloat16 h = __float2bfloat16(v);
        hi[(size_t)n * 1024 + k] = h;
        lo[(size_t)n * 1024 + k] = __float2bfloat16(v - __bfloat162float(h));
    }
}

// ================= mma.sync bf16-split GEMM core (128x64, 3 CTA/SM) =========
#define GK 40
#define G_AH 0
#define G_AL 10240
#define G_BH 20480
#define G_BL 25600
#define G_STAGE 30720
#define GEMM_SMEM (2 * G_STAGE)          // 61440

static __device__ __forceinline__ void gemm_core(
    const __nv_bfloat16* __restrict__ Ahi, const __nv_bfloat16* __restrict__ Alo,
    const __nv_bfloat16* __restrict__ Bhi, const __nv_bfloat16* __restrict__ Blo,
    const float* __restrict__ bias, float* __restrict__ Cf,
    __nv_bfloat16* __restrict__ Ch, __nv_bfloat16* __restrict__ Cl, int mode,
    char* sm)
{
    const uint32_t smb = smem_u32(sm);
    const int tid    = threadIdx.x;
    const int lane   = tid & 31;
    const int warp   = tid >> 5;
    const int warp_m = warp >> 1;
    const int warp_n = warp & 1;
    const int m0 = blockIdx.x * 128;
    const int n0 = blockIdx.y * 64;

    const uint32_t aoff = ((warp_m * 64 + (lane & 15)) * GK + ((lane >> 4) * 8)) * 2;
    const uint32_t boff4 = ((warp_n * 32 + ((lane >> 4) & 1) * 8 + (lane & 7)) * GK
                            + ((lane >> 3) & 1) * 8) * 2;

    float acc[4][4][4] = {};

    auto issue = [&](int c) {
        const uint32_t sb = smb + (c & 1) * G_STAGE;
        const int k0 = c * 32;
        #pragma unroll
        for (int j = 0; j < 4; j++) {
            int lin = tid + j * 128;
            int row = lin >> 2;
            int cg  = lin & 3;
            uint32_t so = (uint32_t)(row * 80 + cg * 16);
            size_t ga = (size_t)(m0 + row) * DD + k0 + cg * 8;
            CP_ASYNC16(sb + G_AH + so, Ahi + ga);
            CP_ASYNC16(sb + G_AL + so, Alo + ga);
        }
        #pragma unroll
        for (int j = 0; j < 2; j++) {
            int lin = tid + j * 128;
            int row = lin >> 2;
            int cg  = lin & 3;
            uint32_t so = (uint32_t)(row * 80 + cg * 16);
            size_t gb = (size_t)(n0 + row) * DD + k0 + cg * 8;
            CP_ASYNC16(sb + G_BH + so, Bhi + gb);
            CP_ASYNC16(sb + G_BL + so, Blo + gb);
        }
    };

    issue(0);
    CP_COMMIT();

    for (int c = 0; c < DD / 32; c++) {
        if (c + 1 < DD / 32) {
            issue(c + 1);
            CP_COMMIT();
            CP_WAIT(1);
        } else {
            CP_WAIT(0);
        }
        __syncthreads();

        const uint32_t sb = smb + (c & 1) * G_STAGE;
        #pragma unroll
        for (int kk = 0; kk < 2; kk++) {
            const uint32_t kby = kk * 32;
            uint32_t ah[4][4], al[4][4];
            #pragma unroll
            for (int mf = 0; mf < 4; mf++) {
                uint32_t ra = sb + aoff + (uint32_t)(mf * 16 * 80) + kby;
                LDSM_X4(ah[mf], ra + G_AH);
                LDSM_X4(al[mf], ra + G_AL);
            }
            uint32_t bh4[2][4], bl4[2][4];
            #pragma unroll
            for (int nfp = 0; nfp < 2; nfp++) {
                uint32_t rb = sb + boff4 + (uint32_t)(nfp * 16 * 80) + kby;
                LDSM_X4(bh4[nfp], rb + G_BH);
                LDSM_X4(bl4[nfp], rb + G_BL);
            }
            #pragma unroll
            for (int mf = 0; mf < 4; mf++)
                #pragma unroll
                for (int nf = 0; nf < 4; nf++) {
                    uint32_t* bh = &bh4[nf >> 1][(nf & 1) * 2];
                    uint32_t* bl = &bl4[nf >> 1][(nf & 1) * 2];
                    MMA16816(acc[mf][nf], ah[mf], bh);
                    MMA16816(acc[mf][nf], ah[mf], bl);
                    MMA16816(acc[mf][nf], al[mf], bh);
                }
        }
        __syncthreads();
    }

    const int lr = lane >> 2;
    const int lc = (lane & 3) * 2;
    #pragma unroll
    for (int mf = 0; mf < 4; mf++) {
        #pragma unroll
        for (int nf = 0; nf < 4; nf++) {
            int n = n0 + warp_n * 32 + nf * 8 + lc;
            float bv0 = bias[n], bv1 = bias[n + 1];
            #pragma unroll
            for (int half = 0; half < 2; half++) {
                int m = m0 + warp_m * 64 + mf * 16 + lr + half * 8;
                float x = acc[mf][nf][half * 2 + 0] + bv0;
                float y = acc[mf][nf][half * 2 + 1] + bv1;
                if (mode == 1) {
                    *(float2*)(Cf + (size_t)m * DD + n) = make_float2(x, y);
                } else {
                    uint32_t phi, plo;
                    split_bf2(x, y, phi, plo);
                    int bidx = m >> 10, s = m & 1023;
                    int h = n >> 6, e = n & 63;
                    if (mode == 0) {
                        size_t off = (((size_t)bidx * HH + h) * SS + s) * DH + e;
                        *(uint32_t*)(Ch + off) = phi;
                        *(uint32_t*)(Cl + off) = plo;
                    } else {
                        size_t off = (((size_t)bidx * HH + h) * DH + e) * SS + s;
                        Ch[off]      = *(__nv_bfloat16*)&phi;
                        Ch[off + SS] = ((__nv_bfloat16*)&phi)[1];
                        Cl[off]      = *(__nv_bfloat16*)&plo;
                        Cl[off + SS] = ((__nv_bfloat16*)&plo)[1];
                    }
                }
            }
        }
    }
}

__global__ __launch_bounds__(128, 3) void qkv_gemm_kernel(
    const float* __restrict__ bq, const float* __restrict__ bk,
    const float* __restrict__ bv)
{
    extern __shared__ char sm[];
    const int z = blockIdx.z;
    if (z == 0)
        gemm_core(g_q_hi, g_q_lo, g_wq_hi, g_wq_lo, bq, nullptr, g_qph, g_qpl, 0, sm);
    else if (z == 1)
        gemm_core(g_k_hi, g_k_lo, g_wk_hi, g_wk_lo, bk, nullptr, g_kph, g_kpl, 0, sm);
    else
        gemm_core(g_v_hi, g_v_lo, g_wv_hi, g_wv_lo, bv, nullptr, g_vth, g_vtl, 2, sm);
}

__global__ __launch_bounds__(128, 3) void outproj_gemm_kernel(
    const float* __restrict__ bo, float* __restrict__ out)
{
    extern __shared__ char sm[];
    gemm_core(g_cx_hi, g_cx_lo, g_wo_hi, g_wo_lo, bo, out, nullptr, nullptr, 1, sm);
}

// ================= fused single-pass attention (R15 config, .cg score) =======
#define ATT_STR 72                       // row stride in bf16 elems (144 B)
#define AQ_H 0                           // q hi: 32*144 = 4608
#define AQ_L 4608
#define AKV 9216                         // 2 stages of 36864
#define OFF_KH 0
#define OFF_KL 9216
#define OFF_VH 18432
#define OFF_VL 27648
#define KV_STAGE 36864
#define ATT_SMEM (AKV + 2 * KV_STAGE)    // 82944

__global__ __launch_bounds__(256, 2) void attn_kernel(float* __restrict__ score_out)
{
    extern __shared__ char sm[];
    __shared__ float s_part[8][16];
    __shared__ float s_inv[32];
    const uint32_t smb = smem_u32(sm);

    const int bh  = blockIdx.y;
    const int q0  = blockIdx.x * 32;
    const int tid = threadIdx.x;
    const int lane = tid & 31;
    const int w    = tid >> 5;
    const int qh   = w >> 2;     // q half: rows qh*16..+16
    const int kq   = w & 3;      // key quarter: keys kq*16..+16 within 64-chunk

    const __nv_bfloat16* qph = g_qph + (size_t)bh * SS * DH;
    const __nv_bfloat16* qpl = g_qpl + (size_t)bh * SS * DH;
    const __nv_bfloat16* kph = g_kph + (size_t)bh * SS * DH;
    const __nv_bfloat16* kpl = g_kpl + (size_t)bh * SS * DH;
    const __nv_bfloat16* vth = g_vth + (size_t)bh * DH * SS;
    const __nv_bfloat16* vtl = g_vtl + (size_t)bh * DH * SS;

    // ---- load q tile (32 x 64) hi/lo into smem ----
    {
        int row = tid >> 3, grp = tid & 7;
        size_t src = (size_t)(q0 + row) * DH + grp * 8;
        uint32_t dst = (uint32_t)(row * 144 + grp * 16);
        *(uint4*)(sm + AQ_H + dst) = *(const uint4*)(qph + src);
        *(uint4*)(sm + AQ_L + dst) = *(const uint4*)(qpl + src);
    }

    const uint32_t a_off = ((qh * 16 + (lane & 15)) * ATT_STR + (lane >> 4) * 8) * 2;
    const uint32_t bk4_off = ((kq * 16 + ((lane >> 4) & 1) * 8 + (lane & 7)) * ATT_STR
                              + ((lane >> 3) & 1) * 8) * 2;
    const uint32_t bv4_off = ((((lane >> 4) & 1) * 8 + (lane & 7)) * ATT_STR
                              + ((lane >> 3) & 1) * 8 + kq * 16) * 2;

    auto issueKV = [&](int c) {
        const uint32_t sb = smb + AKV + (c & 1) * KV_STAGE;
        const int c0 = c * 64;
        #pragma unroll
        for (int i = 0; i < 2; i++) {
            int lin = tid + i * 256;       // 0..511
            int row = lin >> 3, grp = lin & 7;
            uint32_t so = (uint32_t)(row * 144 + grp * 16);
            size_t ksrc = (size_t)(c0 + row) * DH + grp * 8;   // K: row=key
            size_t vsrc = (size_t)row * SS + c0 + grp * 8;     // V^T: row=e
            CP_ASYNC16(sb + OFF_KH + so, kph + ksrc);
            CP_ASYNC16(sb + OFF_KL + so, kpl + ksrc);
            CP_ASYNC16(sb + OFF_VH + so, vth + vsrc);
            CP_ASYNC16(sb + OFF_VL + so, vtl + vsrc);
        }
    };

    issueKV(0);
    CP_COMMIT();
    __syncthreads();   // q tile visible to all warps

    // ---- hoist Q fragments into registers (loop-invariant) ----
    uint32_t qfh[4][4], qfl[4][4];
    #pragma unroll
    for (int kk = 0; kk < 4; kk++) {
        uint32_t ra = smb + a_off + kk * 32;
        LDSM_X4(qfh[kk], ra + AQ_H);
        LDSM_X4(qfl[kk], ra + AQ_L);
    }

    float ctx[8][4] = {};
    float psum0 = 0.f, psum1 = 0.f;

    float* grow0 = score_out + ((size_t)bh * SS + q0 + qh * 16 + (lane >> 2)) * SS;
    float* grow1 = grow0 + (size_t)8 * SS;
    const int lc = (lane & 3) * 2;

    for (int c = 0; c < 16; c++) {
        if (c < 15) { issueKV(c + 1); CP_COMMIT(); CP_WAIT(1); }
        else        { CP_WAIT(0); }
        __syncthreads();

        const uint32_t sb = smb + AKV + (c & 1) * KV_STAGE;

        // S = Q K^T for this warp's 16 q-rows x 16 keys
        float sacc[2][4] = {};
        #pragma unroll
        for (int kk = 0; kk < 4; kk++) {
            uint32_t kb4[4], kl4[4];
            uint32_t rb = sb + bk4_off + kk * 32;
            LDSM_X4(kb4, rb + OFF_KH);
            LDSM_X4(kl4, rb + OFF_KL);
            MMA16816(sacc[0], qfh[kk], (kb4));
            MMA16816(sacc[1], qfh[kk], (kb4 + 2));
            MMA16816(sacc[0], qfh[kk], (kl4));
            MMA16816(sacc[1], qfh[kk], (kl4 + 2));
            MMA16816(sacc[0], qfl[kk], (kb4));
            MMA16816(sacc[1], qfl[kk], (kb4 + 2));
        }

        // exp in registers (no max: |logit| < ~4), stream to gmem (L2-resident)
        float e0 = __expf(sacc[0][0] * 0.125f);
        float e1 = __expf(sacc[0][1] * 0.125f);
        float e2 = __expf(sacc[0][2] * 0.125f);
        float e3 = __expf(sacc[0][3] * 0.125f);
        float f0 = __expf(sacc[1][0] * 0.125f);
        float f1 = __expf(sacc[1][1] * 0.125f);
        float f2 = __expf(sacc[1][2] * 0.125f);
        float f3 = __expf(sacc[1][3] * 0.125f);

        int keyb = c * 64 + kq * 16 + lc;
        STG_CG_F2(grow0 + keyb,     e0, e1);
        STG_CG_F2(grow1 + keyb,     e2, e3);
        STG_CG_F2(grow0 + keyb + 8, f0, f1);
        STG_CG_F2(grow1 + keyb + 8, f2, f3);

        psum0 += (e0 + e1) + (f0 + f1);
        psum1 += (e2 + e3) + (f2 + f3);

        uint32_t pah[4], pal[4];
        split_bf2_trunc(e0, e1, pah[0], pal[0]);
        split_bf2_trunc(e2, e3, pah[1], pal[1]);
        split_bf2_trunc(f0, f1, pah[2], pal[2]);
        split_bf2_trunc(f2, f3, pah[3], pal[3]);

        // ctx += P V (k = this warp's 16 keys)
        #pragma unroll
        for (int nf2 = 0; nf2 < 4; nf2++) {
            uint32_t vh4[4], vl4[4];
            uint32_t rb = sb + bv4_off + (uint32_t)(nf2 * 16 * 144);
            LDSM_X4(vh4, rb + OFF_VH);
            LDSM_X4(vl4, rb + OFF_VL);
            MMA16816(ctx[2 * nf2],     pah, (vh4));
            MMA16816(ctx[2 * nf2 + 1], pah, (vh4 + 2));
            MMA16816(ctx[2 * nf2],     pah, (vl4));
            MMA16816(ctx[2 * nf2 + 1], pah, (vl4 + 2));
            MMA16816(ctx[2 * nf2],     pal, (vh4));
            MMA16816(ctx[2 * nf2 + 1], pal, (vh4 + 2));
        }
        __syncthreads();
    }

    __threadfence();   // score exp writes visible before read-back

    // ---- row-sum reduce -> s_part ----
    psum0 += __shfl_xor_sync(0xFFFFFFFFu, psum0, 1);
    psum0 += __shfl_xor_sync(0xFFFFFFFFu, psum0, 2);
    psum1 += __shfl_xor_sync(0xFFFFFFFFu, psum1, 1);
    psum1 += __shfl_xor_sync(0xFFFFFFFFu, psum1, 2);
    if ((lane & 3) == 0) {
        s_part[w][lane >> 2]       = psum0;
        s_part[w][(lane >> 2) + 8] = psum1;
    }

    // ---- ctx partials to smem (overlay KV stages) ----
    float* red = (float*)(sm + AKV);
    {
        int rl = lane >> 2;
        #pragma unroll
        for (int nf = 0; nf < 8; nf++) {
            int col = nf * 8 + lc;
            *(float2*)&red[w * 1024 + rl * 64 + col] =
                make_float2(ctx[nf][0], ctx[nf][1]);
            *(float2*)&red[w * 1024 + (rl + 8) * 64 + col] =
                make_float2(ctx[nf][2], ctx[nf][3]);
        }
    }
    __syncthreads();

    if (tid < 32) {
        int qhh = tid >> 4, lr = tid & 15;
        float s = s_part[qhh * 4 + 0][lr] + s_part[qhh * 4 + 1][lr]
                + s_part[qhh * 4 + 2][lr] + s_part[qhh * 4 + 3][lr];
        s_inv[tid] = 1.f / s;
    }
    __syncthreads();

    // ---- combine ctx, normalize, write bf16 hi/lo ----
    {
        int row = tid >> 3;              // 0..31
        int cg  = (tid & 7) * 8;
        int qhh = row >> 4, lr = row & 15;
        float iv = s_inv[row];
        float o[8];
        #pragma unroll
        for (int j = 0; j < 8; j++) {
            o[j] = (red[(qhh * 4 + 0) * 1024 + lr * 64 + cg + j]
                  + red[(qhh * 4 + 1) * 1024 + lr * 64 + cg + j]
                  + red[(qhh * 4 + 2) * 1024 + lr * 64 + cg + j]
                  + red[(qhh * 4 + 3) * 1024 + lr * 64 + cg + j]) * iv;
        }
        const int b = bh >> 4;
        const int h = bh & 15;
        size_t off = ((size_t)b * SS + q0 + row) * DD + h * DH + cg;
        __align__(16) __nv_bfloat16 hb[8], lb[8];
        #pragma unroll
        for (int j = 0; j < 8; j++) {
            hb[j] = __float2bfloat16(o[j]);
            lb[j] = __float2bfloat16(o[j] - __bfloat162float(hb[j]));
        }
        *(uint4*)(g_cx_hi + off) = *(uint4*)hb;
        *(uint4*)(g_cx_lo + off) = *(uint4*)lb;
    }

    // ---- score normalize epilogue (L2 read-back) ----
    {
        float* base = score_out + ((size_t)bh * SS + q0) * SS;
        for (int i = tid; i < 32 * 256; i += 256) {
            int row = i >> 8, g4 = i & 255;
            float4* p = (float4*)(base + (size_t)row * SS) + g4;
            float4 v = __ldcg(p);
            float iv = s_inv[row];
            v.x *= iv; v.y *= iv; v.z *= iv; v.w *= iv;
            __stcs(p, v);
        }
    }
}

// ============================================================
extern "C" void kernel_launch(void* const* d_in, const int* in_sizes, int n_in,
                              void* d_out, int out_size)
{
    const float* q  = (const float*)d_in[0];
    const float* k  = (const float*)d_in[1];
    const float* v  = (const float*)d_in[2];
    const float* Wq = (const float*)d_in[3];
    const float* bq = (const float*)d_in[4];
    const float* Wk = (const float*)d_in[5];
    const float* bk = (const float*)d_in[6];
    const float* Wv = (const float*)d_in[7];
    const float* bv = (const float*)d_in[8];
    const float* Wo = (const float*)d_in[9];
    const float* bo = (const float*)d_in[10];

    float* out   = (float*)d_out;
    float* score = out + (size_t)BB * SS * DD;

    cudaFuncSetAttribute(attn_kernel,
                         cudaFuncAttributeMaxDynamicSharedMemorySize, ATT_SMEM);
    cudaFuncSetAttribute(qkv_gemm_kernel,
                         cudaFuncAttributeMaxDynamicSharedMemorySize, GEMM_SMEM);
    cudaFuncSetAttribute(outproj_gemm_kernel,
                         cudaFuncAttributeMaxDynamicSharedMemorySize, GEMM_SMEM);

    // launch 1: activation conversions (fused)
    {
        dim3 g(MTOT * DD / 1024, 3);
        cvt_split_kernel<<<g, 256>>>(q, k, v);
    }
    // launch 2: all weight conversions (fused)
    {
        dim3 g(32, 32, 4), b(32, 8);
        cvt_wt4_kernel<<<g, b>>>(Wq, Wk, Wv, Wo);
    }
    // launch 3: fused QKV projections
    {
        dim3 g(MTOT / 128, DD / 64, 3);
        qkv_gemm_kernel<<<g, 128, GEMM_SMEM>>>(bq, bk, bv);
    }
    // launch 4: fused single-pass attention
    {
        dim3 g(SS / 32, BB * HH);
        attn_kernel<<<g, 256, ATT_SMEM>>>(score);
    }
    // launch 5: output projection
    {
        dim3 g(MTOT / 128, DD / 64);
        outproj_gemm_kernel<<<g, 128, GEMM_SMEM>>>(bo, out);
    }
}